// round 1
// baseline (speedup 1.0000x reference)
#include <cuda_runtime.h>
#include <math.h>

#define BATCH  4
#define SEQ    2048
#define DMODEL 1024
#define NHEADS 16
#define HDIM   64
#define MROWS  (BATCH * SEQ)

// Scratch (allocation-free): Q, K, V, attention output
__device__ float g_q[MROWS * DMODEL];
__device__ float g_k[MROWS * DMODEL];
__device__ float g_v[MROWS * DMODEL];
__device__ float g_o[MROWS * DMODEL];

// ---------------------------------------------------------------------------
// SGEMM: C[M,N] = A[M,K] @ B[N,K]^T   (M=8192, N=K=1024)
// 128x128 block tile, BK=16, 256 threads, 8x8 per-thread micro-tile.
// ---------------------------------------------------------------------------
__global__ __launch_bounds__(256, 2)
void gemm_nt_kernel(const float* __restrict__ A,
                    const float* __restrict__ Bw,
                    float* __restrict__ C) {
    const int M = MROWS, N = DMODEL, K = DMODEL;
    const int BM = 128, BN = 128, BK = 16;

    __shared__ float As[BK][BM];
    __shared__ float Bs[BK][BN];

    const int tid = threadIdx.x;
    const int m0 = blockIdx.y * BM;
    const int n0 = blockIdx.x * BN;
    const int tx = tid & 15;   // 0..15  -> column group
    const int ty = tid >> 4;   // 0..15  -> row group

    float acc[8][8];
#pragma unroll
    for (int i = 0; i < 8; i++)
#pragma unroll
        for (int j = 0; j < 8; j++) acc[i][j] = 0.0f;

    for (int k0 = 0; k0 < K; k0 += BK) {
        // Load A tile (128x16) and B tile (128x16), 2 float4 each per thread.
#pragma unroll
        for (int i = 0; i < 2; i++) {
            int idx = tid + i * 256;        // 0..511
            int row = idx >> 2;             // 0..127
            int c4  = idx & 3;              // 0..3
            float4 va = *(const float4*)&A [(size_t)(m0 + row) * K + k0 + c4 * 4];
            As[c4 * 4 + 0][row] = va.x;
            As[c4 * 4 + 1][row] = va.y;
            As[c4 * 4 + 2][row] = va.z;
            As[c4 * 4 + 3][row] = va.w;
            float4 vb = *(const float4*)&Bw[(size_t)(n0 + row) * K + k0 + c4 * 4];
            Bs[c4 * 4 + 0][row] = vb.x;
            Bs[c4 * 4 + 1][row] = vb.y;
            Bs[c4 * 4 + 2][row] = vb.z;
            Bs[c4 * 4 + 3][row] = vb.w;
        }
        __syncthreads();

#pragma unroll
        for (int k = 0; k < BK; k++) {
            float a[8], b[8];
            *(float4*)&a[0] = *(const float4*)&As[k][ty * 8];
            *(float4*)&a[4] = *(const float4*)&As[k][ty * 8 + 4];
            *(float4*)&b[0] = *(const float4*)&Bs[k][tx * 8];
            *(float4*)&b[4] = *(const float4*)&Bs[k][tx * 8 + 4];
#pragma unroll
            for (int i = 0; i < 8; i++)
#pragma unroll
                for (int j = 0; j < 8; j++)
                    acc[i][j] += a[i] * b[j];
        }
        __syncthreads();
    }

#pragma unroll
    for (int i = 0; i < 8; i++) {
        float4 c0 = make_float4(acc[i][0], acc[i][1], acc[i][2], acc[i][3]);
        float4 c1 = make_float4(acc[i][4], acc[i][5], acc[i][6], acc[i][7]);
        size_t base = (size_t)(m0 + ty * 8 + i) * N + n0 + tx * 8;
        *(float4*)&C[base]     = c0;
        *(float4*)&C[base + 4] = c1;
    }
}

// ---------------------------------------------------------------------------
// Flash attention (causal + key padding mask), fp32.
// grid: (SEQ/128, NHEADS, BATCH), block: 128 threads, 1 thread per query row.
// Q/acc in registers, KV tiles of 32 rows in shared (broadcast reads).
// Output written in (b, s, h, d) order -> contiguous (B*S, D) for out-proj.
// ---------------------------------------------------------------------------
__global__ __launch_bounds__(128)
void flash_kernel(const float* __restrict__ Q,
                  const float* __restrict__ Kp,
                  const float* __restrict__ Vp,
                  const int*   __restrict__ am,
                  float* __restrict__ O) {
    const int BQ = 128, BKV = 32;
    const int qt = blockIdx.x;
    const int h  = blockIdx.y;
    const int b  = blockIdx.z;
    const int q0 = qt * BQ;
    const int tid = threadIdx.x;
    const int qi  = q0 + tid;                 // this thread's query row

    __shared__ float Ks[BKV][HDIM];
    __shared__ float Vs[BKV][HDIM];
    __shared__ float Ms[BKV];                 // 0 or -1e30 additive mask

    const float inv_scale = 0.125f;           // 1/sqrt(64)

    // Load Q row into registers, pre-scaled.
    float q[HDIM];
    {
        const float* qrow = Q + ((size_t)(b * SEQ + qi)) * DMODEL + h * HDIM;
#pragma unroll
        for (int d = 0; d < HDIM; d += 4) {
            float4 v = *(const float4*)&qrow[d];
            q[d]     = v.x * inv_scale;
            q[d + 1] = v.y * inv_scale;
            q[d + 2] = v.z * inv_scale;
            q[d + 3] = v.w * inv_scale;
        }
    }

    float acc[HDIM];
#pragma unroll
    for (int d = 0; d < HDIM; d++) acc[d] = 0.0f;
    float m_run = -1e30f;
    float l_run = 0.0f;

    const int kend = q0 + BQ;                 // causal: keys < kend needed by block

    for (int k0 = 0; k0 < kend; k0 += BKV) {
        // Cooperative tile load: 32x64 K and V, 4 float4 per thread each.
#pragma unroll
        for (int i = 0; i < 4; i++) {
            int idx = tid + i * 128;          // 0..511
            int row = idx >> 4;               // 0..31
            int c4  = idx & 15;               // 0..15
            size_t gbase = ((size_t)(b * SEQ + k0 + row)) * DMODEL + h * HDIM + c4 * 4;
            *(float4*)&Ks[row][c4 * 4] = *(const float4*)&Kp[gbase];
            *(float4*)&Vs[row][c4 * 4] = *(const float4*)&Vp[gbase];
        }
        if (tid < BKV)
            Ms[tid] = (am[b * SEQ + k0 + tid] != 0) ? 0.0f : -1e30f;
        __syncthreads();

        // Scores for all 32 keys (fixed bounds -> registers, no local spill).
        float sc[BKV];
        float tmax = -1e30f;
#pragma unroll
        for (int j = 0; j < BKV; j++) {
            float s = 0.0f;
#pragma unroll
            for (int d = 0; d < HDIM; d += 4) {
                float4 kv = *(const float4*)&Ks[j][d];
                s += q[d] * kv.x + q[d + 1] * kv.y + q[d + 2] * kv.z + q[d + 3] * kv.w;
            }
            s = (k0 + j <= qi) ? (s + Ms[j]) : -1e30f;   // causal + padding mask
            sc[j] = s;
            tmax = fmaxf(tmax, s);
        }

        float m_new = fmaxf(m_run, tmax);
        float corr  = __expf(m_run - m_new);  // ==1 when tile fully masked
        m_run = m_new;
        l_run *= corr;
#pragma unroll
        for (int d = 0; d < HDIM; d++) acc[d] *= corr;

#pragma unroll
        for (int j = 0; j < BKV; j++) {
            float p = __expf(sc[j] - m_run);  // underflows to 0 for masked keys
            l_run += p;
#pragma unroll
            for (int d = 0; d < HDIM; d += 4) {
                float4 vv = *(const float4*)&Vs[j][d];
                acc[d]     += p * vv.x;
                acc[d + 1] += p * vv.y;
                acc[d + 2] += p * vv.z;
                acc[d + 3] += p * vv.w;
            }
        }
        __syncthreads();
    }

    float invl = 1.0f / l_run;
    float* orow = O + ((size_t)(b * SEQ + qi)) * DMODEL + h * HDIM;
#pragma unroll
    for (int d = 0; d < HDIM; d += 4) {
        float4 v = make_float4(acc[d] * invl, acc[d + 1] * invl,
                               acc[d + 2] * invl, acc[d + 3] * invl);
        *(float4*)&orow[d] = v;
    }
}

// ---------------------------------------------------------------------------
extern "C" void kernel_launch(void* const* d_in, const int* in_sizes, int n_in,
                              void* d_out, int out_size) {
    const float* x  = (const float*)d_in[0];
    const int*   am = (const int*)  d_in[1];
    const float* wq = (const float*)d_in[2];
    const float* wk = (const float*)d_in[3];
    const float* wv = (const float*)d_in[4];
    const float* wo = (const float*)d_in[5];
    float* out = (float*)d_out;

    float *q, *k, *v, *o;
    cudaGetSymbolAddress((void**)&q, g_q);
    cudaGetSymbolAddress((void**)&k, g_k);
    cudaGetSymbolAddress((void**)&v, g_v);
    cudaGetSymbolAddress((void**)&o, g_o);

    dim3 gg(DMODEL / 128, MROWS / 128);   // (8, 64)
    gemm_nt_kernel<<<gg, 256>>>(x, wq, q);
    gemm_nt_kernel<<<gg, 256>>>(x, wk, k);
    gemm_nt_kernel<<<gg, 256>>>(x, wv, v);

    dim3 fg(SEQ / 128, NHEADS, BATCH);    // (16, 16, 4)
    flash_kernel<<<fg, 128>>>(q, k, v, am, o);

    gemm_nt_kernel<<<gg, 256>>>(o, wo, out);
}

// round 3
// speedup vs baseline: 1.2581x; 1.2581x over previous
#include <cuda_runtime.h>
#include <cstdint>
#include <math.h>

#define BATCH  4
#define SEQ    2048
#define DMODEL 1024
#define NHEADS 16
#define HDIM   64
#define MROWS  (BATCH * SEQ)

// Scratch (allocation-free): Q, K, V, attention output
__device__ float g_q[MROWS * DMODEL];
__device__ float g_k[MROWS * DMODEL];
__device__ float g_v[MROWS * DMODEL];
__device__ float g_o[MROWS * DMODEL];

// ---------------------------------------------------------------------------
// TF32 helpers (plain sm_103-compatible: Ampere-era mma.sync, no tcgen05)
// ---------------------------------------------------------------------------
__device__ __forceinline__ uint32_t f2tf32(float x) {
    uint32_t u;
    asm("cvt.rna.tf32.f32 %0, %1;" : "=r"(u) : "f"(x));
    return u;
}

__device__ __forceinline__ void mma_tf32_16n8k8(float* c, const uint32_t* a,
                                                const uint32_t* b) {
    asm volatile(
        "mma.sync.aligned.m16n8k8.row.col.f32.tf32.tf32.f32 "
        "{%0,%1,%2,%3}, {%4,%5,%6,%7}, {%8,%9}, {%0,%1,%2,%3};"
        : "+f"(c[0]), "+f"(c[1]), "+f"(c[2]), "+f"(c[3])
        : "r"(a[0]), "r"(a[1]), "r"(a[2]), "r"(a[3]), "r"(b[0]), "r"(b[1]));
}

// ===========================================================================
// Tensor-core TF32 GEMM:  C[M,1024] = A[M,1024] @ B[1024,1024]^T
// (A row-major, B torch-style [N][K] -> exactly mma .row.col)
// CTA tile 128x128, BK=32, 8 warps (2x4), warp tile 64x32 = 4x4 m16n8k8.
// Shared stride 36 floats -> conflict-free fragment loads.
// ===========================================================================
#define GBM 128
#define GBN 128
#define GBK 32
#define SSTR 36

__global__ __launch_bounds__(256, 1)
void gemm_tc_kernel(const float* __restrict__ A,
                    const float* __restrict__ Bw,
                    float* __restrict__ C) {
    const int K = DMODEL, N = DMODEL;
    __shared__ uint32_t As[GBM * SSTR];
    __shared__ uint32_t Bs[GBN * SSTR];

    const int tid = threadIdx.x;
    const int wid = tid >> 5;
    const int lid = tid & 31;
    const int gid = lid >> 2;     // 0..7
    const int tig = lid & 3;      // 0..3
    const int wm  = wid >> 2;     // 0..1 : 64-row slab
    const int wn  = wid & 3;      // 0..3 : 32-col slab
    const int m0  = blockIdx.y * GBM;
    const int n0  = blockIdx.x * GBN;

    float acc[4][4][4];
#pragma unroll
    for (int i = 0; i < 4; i++)
#pragma unroll
        for (int j = 0; j < 4; j++)
#pragma unroll
            for (int r = 0; r < 4; r++) acc[i][j][r] = 0.0f;

    // Per-thread global-load slots: 4 float4 from A, 4 from B per chunk.
    const int ld_row = tid >> 1;                   // 0..127
    const int ld_c4a = (tid & 1) * 4;              // float4 index base (0 or 4)

    float4 pa[4], pb[4];
    {
        const float* Ag = A  + (size_t)(m0 + ld_row) * K;
        const float* Bg = Bw + (size_t)(n0 + ld_row) * K;
#pragma unroll
        for (int i = 0; i < 4; i++) {
            pa[i] = *(const float4*)(Ag + (size_t)((ld_c4a + (i & 1)) * 4 + (i >> 1) ? 0 : 0));
        }
        // (placeholder overwritten below)
    }

    // --- clean prefetch of chunk 0 ---
    {
        const float* Ag = A  + (size_t)(m0 + ld_row) * K;
        const float* Bg = Bw + (size_t)(n0 + ld_row) * K;
#pragma unroll
        for (int i = 0; i < 4; i++) {
            int c4 = ld_c4a + i;                   // 0..7
            pa[i] = *(const float4*)(Ag + c4 * 4);
            pb[i] = *(const float4*)(Bg + c4 * 4);
        }
    }

    const int NCH = K / GBK;                       // 32
    for (int ck = 0; ck < NCH; ck++) {
        // Store prefetched chunk to shared (convert to TF32 bits).
#pragma unroll
        for (int i = 0; i < 4; i++) {
            int c4 = ld_c4a + i;
            uint32_t* da = &As[ld_row * SSTR + c4 * 4];
            da[0] = f2tf32(pa[i].x); da[1] = f2tf32(pa[i].y);
            da[2] = f2tf32(pa[i].z); da[3] = f2tf32(pa[i].w);
            uint32_t* db = &Bs[ld_row * SSTR + c4 * 4];
            db[0] = f2tf32(pb[i].x); db[1] = f2tf32(pb[i].y);
            db[2] = f2tf32(pb[i].z); db[3] = f2tf32(pb[i].w);
        }
        __syncthreads();

        // Prefetch next chunk while computing this one.
        if (ck + 1 < NCH) {
            const int k1 = (ck + 1) * GBK;
            const float* Ag = A  + (size_t)(m0 + ld_row) * K + k1;
            const float* Bg = Bw + (size_t)(n0 + ld_row) * K + k1;
#pragma unroll
            for (int i = 0; i < 4; i++) {
                int c4 = ld_c4a + i;
                pa[i] = *(const float4*)(Ag + c4 * 4);
                pb[i] = *(const float4*)(Bg + c4 * 4);
            }
        }

#pragma unroll
        for (int kk = 0; kk < 4; kk++) {           // 4 x k=8
            const int kb = kk * 8;
            uint32_t af[4][4], bf[4][2];
#pragma unroll
            for (int mt = 0; mt < 4; mt++) {
                int r0 = (wm * 64 + mt * 16 + gid) * SSTR + kb + tig;
                af[mt][0] = As[r0];
                af[mt][1] = As[r0 + 8 * SSTR];
                af[mt][2] = As[r0 + 4];
                af[mt][3] = As[r0 + 8 * SSTR + 4];
            }
#pragma unroll
            for (int nt = 0; nt < 4; nt++) {
                int r0 = (wn * 32 + nt * 8 + gid) * SSTR + kb + tig;
                bf[nt][0] = Bs[r0];
                bf[nt][1] = Bs[r0 + 4];
            }
#pragma unroll
            for (int mt = 0; mt < 4; mt++)
#pragma unroll
                for (int nt = 0; nt < 4; nt++)
                    mma_tf32_16n8k8(acc[mt][nt], af[mt], bf[nt]);
        }
        __syncthreads();
    }

    // Epilogue: each warp writes its 64x32 tile (float2 per fragment half).
#pragma unroll
    for (int mt = 0; mt < 4; mt++) {
#pragma unroll
        for (int nt = 0; nt < 4; nt++) {
            int row = m0 + wm * 64 + mt * 16 + gid;
            int col = n0 + wn * 32 + nt * 8 + 2 * tig;
            float* base0 = &C[(size_t)row * N + col];
            float* base1 = &C[(size_t)(row + 8) * N + col];
            *(float2*)base0 = make_float2(acc[mt][nt][0], acc[mt][nt][1]);
            *(float2*)base1 = make_float2(acc[mt][nt][2], acc[mt][nt][3]);
        }
    }
}

// ---------------------------------------------------------------------------
// Flash attention (causal + key padding mask), fp32 — unchanged this round.
// ---------------------------------------------------------------------------
__global__ __launch_bounds__(128)
void flash_kernel(const float* __restrict__ Q,
                  const float* __restrict__ Kp,
                  const float* __restrict__ Vp,
                  const int*   __restrict__ am,
                  float* __restrict__ O) {
    const int BQ = 128, BKV = 32;
    const int qt = blockIdx.x;
    const int h  = blockIdx.y;
    const int b  = blockIdx.z;
    const int q0 = qt * BQ;
    const int tid = threadIdx.x;
    const int qi  = q0 + tid;

    __shared__ float Ks[BKV][HDIM];
    __shared__ float Vs[BKV][HDIM];
    __shared__ float Ms[BKV];

    const float inv_scale = 0.125f;

    float q[HDIM];
    {
        const float* qrow = Q + ((size_t)(b * SEQ + qi)) * DMODEL + h * HDIM;
#pragma unroll
        for (int d = 0; d < HDIM; d += 4) {
            float4 v = *(const float4*)&qrow[d];
            q[d]     = v.x * inv_scale;
            q[d + 1] = v.y * inv_scale;
            q[d + 2] = v.z * inv_scale;
            q[d + 3] = v.w * inv_scale;
        }
    }

    float acc[HDIM];
#pragma unroll
    for (int d = 0; d < HDIM; d++) acc[d] = 0.0f;
    float m_run = -1e30f;
    float l_run = 0.0f;

    const int kend = q0 + BQ;

    for (int k0 = 0; k0 < kend; k0 += BKV) {
#pragma unroll
        for (int i = 0; i < 4; i++) {
            int idx = tid + i * 128;
            int row = idx >> 4;
            int c4  = idx & 15;
            size_t gbase = ((size_t)(b * SEQ + k0 + row)) * DMODEL + h * HDIM + c4 * 4;
            *(float4*)&Ks[row][c4 * 4] = *(const float4*)&Kp[gbase];
            *(float4*)&Vs[row][c4 * 4] = *(const float4*)&Vp[gbase];
        }
        if (tid < BKV)
            Ms[tid] = (am[b * SEQ + k0 + tid] != 0) ? 0.0f : -1e30f;
        __syncthreads();

        float sc[BKV];
        float tmax = -1e30f;
#pragma unroll
        for (int j = 0; j < BKV; j++) {
            float s = 0.0f;
#pragma unroll
            for (int d = 0; d < HDIM; d += 4) {
                float4 kv = *(const float4*)&Ks[j][d];
                s += q[d] * kv.x + q[d + 1] * kv.y + q[d + 2] * kv.z + q[d + 3] * kv.w;
            }
            s = (k0 + j <= qi) ? (s + Ms[j]) : -1e30f;
            sc[j] = s;
            tmax = fmaxf(tmax, s);
        }

        float m_new = fmaxf(m_run, tmax);
        float corr  = __expf(m_run - m_new);
        m_run = m_new;
        l_run *= corr;
#pragma unroll
        for (int d = 0; d < HDIM; d++) acc[d] *= corr;

#pragma unroll
        for (int j = 0; j < BKV; j++) {
            float p = __expf(sc[j] - m_run);
            l_run += p;
#pragma unroll
            for (int d = 0; d < HDIM; d += 4) {
                float4 vv = *(const float4*)&Vs[j][d];
                acc[d]     += p * vv.x;
                acc[d + 1] += p * vv.y;
                acc[d + 2] += p * vv.z;
                acc[d + 3] += p * vv.w;
            }
        }
        __syncthreads();
    }

    float invl = 1.0f / l_run;
    float* orow = O + ((size_t)(b * SEQ + qi)) * DMODEL + h * HDIM;
#pragma unroll
    for (int d = 0; d < HDIM; d += 4) {
        float4 v = make_float4(acc[d] * invl, acc[d + 1] * invl,
                               acc[d + 2] * invl, acc[d + 3] * invl);
        *(float4*)&orow[d] = v;
    }
}

// ---------------------------------------------------------------------------
extern "C" void kernel_launch(void* const* d_in, const int* in_sizes, int n_in,
                              void* d_out, int out_size) {
    const float* x  = (const float*)d_in[0];
    const int*   am = (const int*)  d_in[1];
    const float* wq = (const float*)d_in[2];
    const float* wk = (const float*)d_in[3];
    const float* wv = (const float*)d_in[4];
    const float* wo = (const float*)d_in[5];
    float* out = (float*)d_out;

    float *q, *k, *v, *o;
    cudaGetSymbolAddress((void**)&q, g_q);
    cudaGetSymbolAddress((void**)&k, g_k);
    cudaGetSymbolAddress((void**)&v, g_v);
    cudaGetSymbolAddress((void**)&o, g_o);

    dim3 gg(DMODEL / GBN, MROWS / GBM);   // (8, 64)
    gemm_tc_kernel<<<gg, 256>>>(x, wq, q);
    gemm_tc_kernel<<<gg, 256>>>(x, wk, k);
    gemm_tc_kernel<<<gg, 256>>>(x, wv, v);

    dim3 fg(SEQ / 128, NHEADS, BATCH);    // (16, 16, 4)
    flash_kernel<<<fg, 128>>>(q, k, v, am, o);

    gemm_tc_kernel<<<gg, 256>>>(o, wo, out);
}

// round 6
// speedup vs baseline: 1.6206x; 1.2882x over previous
#include <cuda_runtime.h>
#include <cuda_fp16.h>
#include <cstdint>
#include <math.h>

#define BATCH  4
#define SEQ    2048
#define DMODEL 1024
#define NHEADS 16
#define HDIM   64
#define MROWS  (BATCH * SEQ)

// Scratch (allocation-free)
__device__ float  g_q[MROWS * DMODEL];
__device__ float  g_k[MROWS * DMODEL];
__device__ float  g_v[MROWS * DMODEL];
__device__ __half g_xh[MROWS * DMODEL];
__device__ __half g_oh[MROWS * DMODEL];
__device__ __half g_wh[4][DMODEL * DMODEL];   // wq, wk, wv, wo as fp16

// ---------------------------------------------------------------------------
// Helpers
// ---------------------------------------------------------------------------
__device__ __forceinline__ uint32_t smem_u32(const void* p) {
    uint32_t a;
    asm("{ .reg .u64 t; cvta.to.shared.u64 t, %1; cvt.u32.u64 %0, t; }"
        : "=r"(a) : "l"(p));
    return a;
}

__device__ __forceinline__ void cp_async16(uint32_t dst, const void* src) {
    asm volatile("cp.async.cg.shared.global [%0], [%1], 16;"
                 :: "r"(dst), "l"(src));
}
#define CP_COMMIT() asm volatile("cp.async.commit_group;" ::: "memory")
#define CP_WAIT1()  asm volatile("cp.async.wait_group 1;" ::: "memory")
#define CP_WAIT0()  asm volatile("cp.async.wait_group 0;" ::: "memory")

__device__ __forceinline__ void mma_f16_16n8k16(float* c, const uint32_t* a,
                                                const uint32_t* b) {
    asm volatile(
        "mma.sync.aligned.m16n8k16.row.col.f32.f16.f16.f32 "
        "{%0,%1,%2,%3}, {%4,%5,%6,%7}, {%8,%9}, {%0,%1,%2,%3};"
        : "+f"(c[0]), "+f"(c[1]), "+f"(c[2]), "+f"(c[3])
        : "r"(a[0]), "r"(a[1]), "r"(a[2]), "r"(a[3]), "r"(b[0]), "r"(b[1]));
}

// ---------------------------------------------------------------------------
// fp32 -> fp16 converter (vectorized, 4 elems/thread)
// ---------------------------------------------------------------------------
__global__ void f2h_kernel(const float* __restrict__ s, __half* __restrict__ d,
                           int n4) {
    int i = blockIdx.x * blockDim.x + threadIdx.x;
    if (i < n4) {
        float4 v = ((const float4*)s)[i];
        ((__half2*)d)[2 * i]     = __floats2half2_rn(v.x, v.y);
        ((__half2*)d)[2 * i + 1] = __floats2half2_rn(v.z, v.w);
    }
}

// ===========================================================================
// fp16 tensor-core GEMM:  C[M,1024](f32) = A[M,1024](f16) @ B[1024,1024](f16)^T
// (A row-major, B torch-style [N][K] -> mma .row.col directly)
// CTA 128x128, BK=64 halfs, 8 warps (2x4), warp tile 64x32 = 4x4 m16n8k16.
// 2-stage cp.async pipeline; smem stride 72 halfs -> conflict-free LDS.
// ===========================================================================
#define GBM 128
#define GBN 128
#define BKH 64
#define SSTRH 72
#define STAGE_BYTES (2 * 128 * SSTRH * 2)        // A+B per stage = 36864
#define SMEM_GEMM   (2 * STAGE_BYTES)            // 73728

__global__ __launch_bounds__(256)
void gemm_h_kernel(const __half* __restrict__ A,
                   const __half* __restrict__ Bw,
                   float* __restrict__ C) {
    extern __shared__ char smemc[];
    const uint32_t sb = smem_u32(smemc);
    const int K = DMODEL, N = DMODEL;
    const int tid = threadIdx.x;
    const int wid = tid >> 5;
    const int lid = tid & 31;
    const int gid = lid >> 2;        // 0..7
    const int tig = lid & 3;         // 0..3
    const int wm  = wid >> 2;        // 0..1
    const int wn  = wid & 3;         // 0..3
    const int m0  = blockIdx.y * GBM;
    const int n0  = blockIdx.x * GBN;

    float acc[4][4][4];
#pragma unroll
    for (int i = 0; i < 4; i++)
#pragma unroll
        for (int j = 0; j < 4; j++)
#pragma unroll
            for (int r = 0; r < 4; r++) acc[i][j][r] = 0.0f;

    // cp.async issue for one 128x64-half tile pair (A and B), 8 int4/thread.
    auto issue = [&](int stage, int ck) {
        const __half* Ag = A  + (size_t)m0 * K + ck * BKH;
        const __half* Bg = Bw + (size_t)n0 * K + ck * BKH;
        const uint32_t da = sb + stage * STAGE_BYTES;
        const uint32_t db = da + 128 * SSTRH * 2;
#pragma unroll
        for (int i = 0; i < 4; i++) {
            int idx = tid + i * 256;             // 0..1023
            int row = idx >> 3;                  // 0..127
            int c   = idx & 7;                   // int4 within row
            uint32_t so = (uint32_t)(row * SSTRH + c * 8) * 2;
            cp_async16(da + so, Ag + (size_t)row * K + c * 8);
            cp_async16(db + so, Bg + (size_t)row * K + c * 8);
        }
        CP_COMMIT();
    };

    const int NCH = K / BKH;                     // 16
    issue(0, 0);

    for (int ck = 0; ck < NCH; ck++) {
        if (ck + 1 < NCH) { issue((ck + 1) & 1, ck + 1); CP_WAIT1(); }
        else              { CP_WAIT0(); }
        __syncthreads();

        const char* bufA = smemc + (ck & 1) * STAGE_BYTES;
        const char* bufB = bufA + 128 * SSTRH * 2;

#pragma unroll
        for (int kk = 0; kk < 4; kk++) {         // 4 x k16
            const int koff = kk * 16;            // halfs
            uint32_t af[4][4], bf[4][2];
#pragma unroll
            for (int mt = 0; mt < 4; mt++) {
                int ra = (wm * 64 + mt * 16 + gid) * SSTRH + koff + 2 * tig;
                const uint32_t* pa = (const uint32_t*)(bufA + 2 * ra);
                af[mt][0] = pa[0];
                af[mt][1] = pa[8 * SSTRH / 2];   // row + 8
                af[mt][2] = pa[4];               // k + 8
                af[mt][3] = pa[8 * SSTRH / 2 + 4];
            }
#pragma unroll
            for (int nt = 0; nt < 4; nt++) {
                int rb = (wn * 32 + nt * 8 + gid) * SSTRH + koff + 2 * tig;
                const uint32_t* pb = (const uint32_t*)(bufB + 2 * rb);
                bf[nt][0] = pb[0];
                bf[nt][1] = pb[4];               // k + 8
            }
#pragma unroll
            for (int mt = 0; mt < 4; mt++)
#pragma unroll
                for (int nt = 0; nt < 4; nt++)
                    mma_f16_16n8k16(acc[mt][nt], af[mt], bf[nt]);
        }
        __syncthreads();
    }

    // Epilogue: warp writes its 64x32 tile.
#pragma unroll
    for (int mt = 0; mt < 4; mt++) {
#pragma unroll
        for (int nt = 0; nt < 4; nt++) {
            int row = m0 + wm * 64 + mt * 16 + gid;
            int col = n0 + wn * 32 + nt * 8 + 2 * tig;
            *(float2*)&C[(size_t)row * N + col] =
                make_float2(acc[mt][nt][0], acc[mt][nt][1]);
            *(float2*)&C[(size_t)(row + 8) * N + col] =
                make_float2(acc[mt][nt][2], acc[mt][nt][3]);
        }
    }
}

// ---------------------------------------------------------------------------
// Flash attention (causal + key padding mask), fp32 math, fp16 output.
// grid: (SEQ/128, NHEADS, BATCH), block 128, 1 thread per query row.
// ---------------------------------------------------------------------------
__global__ __launch_bounds__(128)
void flash_kernel(const float* __restrict__ Q,
                  const float* __restrict__ Kp,
                  const float* __restrict__ Vp,
                  const int*   __restrict__ am,
                  __half* __restrict__ O) {
    const int BQ = 128, BKV = 32;
    const int qt = blockIdx.x;
    const int h  = blockIdx.y;
    const int b  = blockIdx.z;
    const int q0 = qt * BQ;
    const int tid = threadIdx.x;
    const int qi  = q0 + tid;

    __shared__ float Ks[BKV][HDIM];
    __shared__ float Vs[BKV][HDIM];
    __shared__ float Ms[BKV];

    const float inv_scale = 0.125f;

    float q[HDIM];
    {
        const float* qrow = Q + ((size_t)(b * SEQ + qi)) * DMODEL + h * HDIM;
#pragma unroll
        for (int d = 0; d < HDIM; d += 4) {
            float4 v = *(const float4*)&qrow[d];
            q[d]     = v.x * inv_scale;
            q[d + 1] = v.y * inv_scale;
            q[d + 2] = v.z * inv_scale;
            q[d + 3] = v.w * inv_scale;
        }
    }

    float acc[HDIM];
#pragma unroll
    for (int d = 0; d < HDIM; d++) acc[d] = 0.0f;
    float m_run = -1e30f;
    float l_run = 0.0f;

    const int kend = q0 + BQ;

    for (int k0 = 0; k0 < kend; k0 += BKV) {
#pragma unroll
        for (int i = 0; i < 4; i++) {
            int idx = tid + i * 128;
            int row = idx >> 4;
            int c4  = idx & 15;
            size_t gbase = ((size_t)(b * SEQ + k0 + row)) * DMODEL + h * HDIM + c4 * 4;
            *(float4*)&Ks[row][c4 * 4] = *(const float4*)&Kp[gbase];
            *(float4*)&Vs[row][c4 * 4] = *(const float4*)&Vp[gbase];
        }
        if (tid < BKV)
            Ms[tid] = (am[b * SEQ + k0 + tid] != 0) ? 0.0f : -1e30f;
        __syncthreads();

        float sc[BKV];
        float tmax = -1e30f;
#pragma unroll
        for (int j = 0; j < BKV; j++) {
            float s = 0.0f;
#pragma unroll
            for (int d = 0; d < HDIM; d += 4) {
                float4 kv = *(const float4*)&Ks[j][d];
                s += q[d] * kv.x + q[d + 1] * kv.y + q[d + 2] * kv.z + q[d + 3] * kv.w;
            }
            s = (k0 + j <= qi) ? (s + Ms[j]) : -1e30f;
            sc[j] = s;
            tmax = fmaxf(tmax, s);
        }

        float m_new = fmaxf(m_run, tmax);
        float corr  = __expf(m_run - m_new);
        m_run = m_new;
        l_run *= corr;
#pragma unroll
        for (int d = 0; d < HDIM; d++) acc[d] *= corr;

#pragma unroll
        for (int j = 0; j < BKV; j++) {
            float p = __expf(sc[j] - m_run);
            l_run += p;
#pragma unroll
            for (int d = 0; d < HDIM; d += 4) {
                float4 vv = *(const float4*)&Vs[j][d];
                acc[d]     += p * vv.x;
                acc[d + 1] += p * vv.y;
                acc[d + 2] += p * vv.z;
                acc[d + 3] += p * vv.w;
            }
        }
        __syncthreads();
    }

    float invl = 1.0f / l_run;
    __half2* orow = (__half2*)(O + ((size_t)(b * SEQ + qi)) * DMODEL + h * HDIM);
#pragma unroll
    for (int d = 0; d < HDIM; d += 2)
        orow[d >> 1] = __floats2half2_rn(acc[d] * invl, acc[d + 1] * invl);
}

// ---------------------------------------------------------------------------
extern "C" void kernel_launch(void* const* d_in, const int* in_sizes, int n_in,
                              void* d_out, int out_size) {
    const float* x  = (const float*)d_in[0];
    const int*   am = (const int*)  d_in[1];
    const float* w[4] = { (const float*)d_in[2], (const float*)d_in[3],
                          (const float*)d_in[4], (const float*)d_in[5] };
    float* out = (float*)d_out;

    float *q, *k, *v;
    __half *xh, *oh, *wh;
    cudaGetSymbolAddress((void**)&q,  g_q);
    cudaGetSymbolAddress((void**)&k,  g_k);
    cudaGetSymbolAddress((void**)&v,  g_v);
    cudaGetSymbolAddress((void**)&xh, g_xh);
    cudaGetSymbolAddress((void**)&oh, g_oh);
    cudaGetSymbolAddress((void**)&wh, g_wh);

    cudaFuncSetAttribute(gemm_h_kernel,
                         cudaFuncAttributeMaxDynamicSharedMemorySize, SMEM_GEMM);

    // Convert x + weights to fp16
    {
        int n4 = MROWS * DMODEL / 4;
        f2h_kernel<<<(n4 + 255) / 256, 256>>>(x, xh, n4);
        int w4 = DMODEL * DMODEL / 4;
        for (int i = 0; i < 4; i++)
            f2h_kernel<<<(w4 + 255) / 256, 256>>>(w[i], wh + (size_t)i * DMODEL * DMODEL, w4);
    }

    dim3 gg(DMODEL / GBN, MROWS / GBM);   // (8, 64)
    gemm_h_kernel<<<gg, 256, SMEM_GEMM>>>(xh, wh + 0 * (size_t)DMODEL * DMODEL, q);
    gemm_h_kernel<<<gg, 256, SMEM_GEMM>>>(xh, wh + 1 * (size_t)DMODEL * DMODEL, k);
    gemm_h_kernel<<<gg, 256, SMEM_GEMM>>>(xh, wh + 2 * (size_t)DMODEL * DMODEL, v);

    dim3 fg(SEQ / 128, NHEADS, BATCH);    // (16, 16, 4)
    flash_kernel<<<fg, 128>>>(q, k, v, am, oh);

    gemm_h_kernel<<<gg, 256, SMEM_GEMM>>>(oh, wh + 3 * (size_t)DMODEL * DMODEL, out);
}

// round 7
// speedup vs baseline: 8.4375x; 5.2063x over previous
#include <cuda_runtime.h>
#include <cuda_fp16.h>
#include <cstdint>
#include <math.h>

#define BATCH  4
#define SEQ    2048
#define DMODEL 1024
#define NHEADS 16
#define HDIM   64
#define MROWS  (BATCH * SEQ)

// Scratch (allocation-free)
__device__ __half g_xh[MROWS * DMODEL];
__device__ __half g_qh[MROWS * DMODEL];
__device__ __half g_kh[MROWS * DMODEL];
__device__ __half g_vh[MROWS * DMODEL];
__device__ __half g_vt[MROWS * DMODEL];       // V^T per (b,h): [(b*16+h)*64+d][s]
__device__ __half g_oh[MROWS * DMODEL];
__device__ __half g_wh[4][DMODEL * DMODEL];   // wq, wk, wv, wo as fp16

// ---------------------------------------------------------------------------
// Helpers
// ---------------------------------------------------------------------------
__device__ __forceinline__ uint32_t smem_u32(const void* p) {
    uint32_t a;
    asm("{ .reg .u64 t; cvta.to.shared.u64 t, %1; cvt.u32.u64 %0, t; }"
        : "=r"(a) : "l"(p));
    return a;
}

__device__ __forceinline__ void cp_async16(uint32_t dst, const void* src) {
    asm volatile("cp.async.cg.shared.global [%0], [%1], 16;"
                 :: "r"(dst), "l"(src));
}
#define CP_COMMIT() asm volatile("cp.async.commit_group;" ::: "memory")
#define CP_WAIT1()  asm volatile("cp.async.wait_group 1;" ::: "memory")
#define CP_WAIT0()  asm volatile("cp.async.wait_group 0;" ::: "memory")

__device__ __forceinline__ void mma_f16_16n8k16(float* c, const uint32_t* a,
                                                const uint32_t* b) {
    asm volatile(
        "mma.sync.aligned.m16n8k16.row.col.f32.f16.f16.f32 "
        "{%0,%1,%2,%3}, {%4,%5,%6,%7}, {%8,%9}, {%0,%1,%2,%3};"
        : "+f"(c[0]), "+f"(c[1]), "+f"(c[2]), "+f"(c[3])
        : "r"(a[0]), "r"(a[1]), "r"(a[2]), "r"(a[3]), "r"(b[0]), "r"(b[1]));
}

__device__ __forceinline__ uint32_t h2u(float a, float b) {
    __half2 h = __floats2half2_rn(a, b);
    return *(uint32_t*)&h;
}

// ---------------------------------------------------------------------------
// fp32 -> fp16 converter
// ---------------------------------------------------------------------------
__global__ void f2h_kernel(const float* __restrict__ s, __half* __restrict__ d,
                           int n4) {
    int i = blockIdx.x * blockDim.x + threadIdx.x;
    if (i < n4) {
        float4 v = ((const float4*)s)[i];
        ((__half2*)d)[2 * i]     = __floats2half2_rn(v.x, v.y);
        ((__half2*)d)[2 * i + 1] = __floats2half2_rn(v.z, v.w);
    }
}

// ---------------------------------------------------------------------------
// V transpose: v[b*SEQ+s][h*64+d] -> vt[(b*16+h)*64+d][s]
// ---------------------------------------------------------------------------
__global__ __launch_bounds__(256)
void vtrans_kernel(const __half* __restrict__ v, __half* __restrict__ vt) {
    __shared__ __half t[64][72];
    const int tid = threadIdx.x;
    const int s0 = blockIdx.x * 64;
    const int h  = blockIdx.y;
    const int b  = blockIdx.z;
#pragma unroll
    for (int i = 0; i < 2; i++) {
        int idx = tid + i * 256, row = idx >> 3, c = idx & 7;
        *(int4*)&t[row][c * 8] =
            *(const int4*)&v[((size_t)(b * SEQ) + s0 + row) * DMODEL + h * 64 + c * 8];
    }
    __syncthreads();
#pragma unroll
    for (int i = 0; i < 2; i++) {
        int idx = tid + i * 256, d = idx >> 3, c = idx & 7;
        __half tmp[8];
#pragma unroll
        for (int k = 0; k < 8; k++) tmp[k] = t[c * 8 + k][d];
        *(int4*)&vt[((size_t)((b * 16 + h) * 64) + d) * SEQ + s0 + c * 8] =
            *(int4*)tmp;
    }
}

// ===========================================================================
// fp16 tensor-core GEMM (templated output):
//   C[M,1024] = scale * (A(f16) @ B(f16)^T)
// CTA 128x128, BK=64, 8 warps, warp tile 64x32, 2-stage cp.async.
// ===========================================================================
#define GBM 128
#define GBN 128
#define BKH 64
#define SSTRH 72
#define STAGE_BYTES (2 * 128 * SSTRH * 2)
#define SMEM_GEMM   (2 * STAGE_BYTES)

template <typename OutT>
__global__ __launch_bounds__(256)
void gemm_h_kernel(const __half* __restrict__ A,
                   const __half* __restrict__ Bw,
                   OutT* __restrict__ C, float scale) {
    extern __shared__ char smemc[];
    const uint32_t sb = smem_u32(smemc);
    const int K = DMODEL, N = DMODEL;
    const int tid = threadIdx.x;
    const int wid = tid >> 5;
    const int lid = tid & 31;
    const int gid = lid >> 2;
    const int tig = lid & 3;
    const int wm  = wid >> 2;
    const int wn  = wid & 3;
    const int m0  = blockIdx.y * GBM;
    const int n0  = blockIdx.x * GBN;

    float acc[4][4][4];
#pragma unroll
    for (int i = 0; i < 4; i++)
#pragma unroll
        for (int j = 0; j < 4; j++)
#pragma unroll
            for (int r = 0; r < 4; r++) acc[i][j][r] = 0.0f;

    auto issue = [&](int stage, int ck) {
        const __half* Ag = A  + (size_t)m0 * K + ck * BKH;
        const __half* Bg = Bw + (size_t)n0 * K + ck * BKH;
        const uint32_t da = sb + stage * STAGE_BYTES;
        const uint32_t db = da + 128 * SSTRH * 2;
#pragma unroll
        for (int i = 0; i < 4; i++) {
            int idx = tid + i * 256;
            int row = idx >> 3;
            int c   = idx & 7;
            uint32_t so = (uint32_t)(row * SSTRH + c * 8) * 2;
            cp_async16(da + so, Ag + (size_t)row * K + c * 8);
            cp_async16(db + so, Bg + (size_t)row * K + c * 8);
        }
        CP_COMMIT();
    };

    const int NCH = K / BKH;
    issue(0, 0);

    for (int ck = 0; ck < NCH; ck++) {
        if (ck + 1 < NCH) { issue((ck + 1) & 1, ck + 1); CP_WAIT1(); }
        else              { CP_WAIT0(); }
        __syncthreads();

        const char* bufA = smemc + (ck & 1) * STAGE_BYTES;
        const char* bufB = bufA + 128 * SSTRH * 2;

#pragma unroll
        for (int kk = 0; kk < 4; kk++) {
            const int koff = kk * 16;
            uint32_t af[4][4], bf[4][2];
#pragma unroll
            for (int mt = 0; mt < 4; mt++) {
                int ra = (wm * 64 + mt * 16 + gid) * SSTRH + koff + 2 * tig;
                const uint32_t* pa = (const uint32_t*)(bufA + 2 * ra);
                af[mt][0] = pa[0];
                af[mt][1] = pa[8 * SSTRH / 2];
                af[mt][2] = pa[4];
                af[mt][3] = pa[8 * SSTRH / 2 + 4];
            }
#pragma unroll
            for (int nt = 0; nt < 4; nt++) {
                int rb = (wn * 32 + nt * 8 + gid) * SSTRH + koff + 2 * tig;
                const uint32_t* pb = (const uint32_t*)(bufB + 2 * rb);
                bf[nt][0] = pb[0];
                bf[nt][1] = pb[4];
            }
#pragma unroll
            for (int mt = 0; mt < 4; mt++)
#pragma unroll
                for (int nt = 0; nt < 4; nt++)
                    mma_f16_16n8k16(acc[mt][nt], af[mt], bf[nt]);
        }
        __syncthreads();
    }

#pragma unroll
    for (int mt = 0; mt < 4; mt++) {
#pragma unroll
        for (int nt = 0; nt < 4; nt++) {
            int row = m0 + wm * 64 + mt * 16 + gid;
            int col = n0 + wn * 32 + nt * 8 + 2 * tig;
            if (sizeof(OutT) == 4) {
                float* Cf = (float*)C;
                *(float2*)&Cf[(size_t)row * N + col] =
                    make_float2(acc[mt][nt][0] * scale, acc[mt][nt][1] * scale);
                *(float2*)&Cf[(size_t)(row + 8) * N + col] =
                    make_float2(acc[mt][nt][2] * scale, acc[mt][nt][3] * scale);
            } else {
                __half* Ch = (__half*)C;
                *(__half2*)&Ch[(size_t)row * N + col] =
                    __floats2half2_rn(acc[mt][nt][0] * scale, acc[mt][nt][1] * scale);
                *(__half2*)&Ch[(size_t)(row + 8) * N + col] =
                    __floats2half2_rn(acc[mt][nt][2] * scale, acc[mt][nt][3] * scale);
            }
        }
    }
}

// ===========================================================================
// Tensor-core flash attention (FA2 fragment reuse).
// grid (SEQ/128, NHEADS, BATCH), 128 threads = 4 warps; warp: 32 q-rows.
// Q pre-scaled by 1/8 at projection. BKV=64, double-buffered cp.async.
// ===========================================================================
#define FBKV 64
#define FSTR 72

__global__ __launch_bounds__(128)
void flash_tc_kernel(const __half* __restrict__ Qh,
                     const __half* __restrict__ Kh,
                     const __half* __restrict__ Vt,
                     const int*   __restrict__ am,
                     __half* __restrict__ O) {
    __shared__ __half Ks[2][FBKV * FSTR];
    __shared__ __half Vs[2][FBKV * FSTR];
    __shared__ float  Ms[2][FBKV];

    const int tid = threadIdx.x;
    const int wid = tid >> 5;
    const int lid = tid & 31;
    const int gid = lid >> 2;
    const int tig = lid & 3;
    const int q0  = blockIdx.x * 128;
    const int h   = blockIdx.y;
    const int b   = blockIdx.z;
    const int qw0 = q0 + wid * 32;

    const uint32_t ksa = smem_u32(Ks);
    const uint32_t vsa = smem_u32(Vs);

    // Q fragments: 2 m-tiles x 4 k-tiles.
    uint32_t qf[2][4][4];
#pragma unroll
    for (int mt = 0; mt < 2; mt++)
#pragma unroll
        for (int kt = 0; kt < 4; kt++) {
            const __half* base = Qh + ((size_t)(b * SEQ) + qw0 + mt * 16 + gid) * DMODEL
                                    + h * 64 + kt * 16 + 2 * tig;
            qf[mt][kt][0] = *(const uint32_t*)base;
            qf[mt][kt][1] = *(const uint32_t*)(base + 8 * DMODEL);
            qf[mt][kt][2] = *(const uint32_t*)(base + 8);
            qf[mt][kt][3] = *(const uint32_t*)(base + 8 * DMODEL + 8);
        }

    float o[2][8][4];
#pragma unroll
    for (int mt = 0; mt < 2; mt++)
#pragma unroll
        for (int nt = 0; nt < 8; nt++)
#pragma unroll
            for (int r = 0; r < 4; r++) o[mt][nt][r] = 0.0f;
    float m_run[2][2] = { { -1e30f, -1e30f }, { -1e30f, -1e30f } };
    float lp[2][2]    = { { 0.0f, 0.0f }, { 0.0f, 0.0f } };

    const int nkb = (q0 + 128) / FBKV;

    auto issue = [&](int buf, int kb) {
        const int kv0 = kb * FBKV;
#pragma unroll
        for (int i = 0; i < 4; i++) {
            int idx = tid + i * 128;
            int row = idx >> 3;
            int c   = idx & 7;
            uint32_t so = (uint32_t)(buf * FBKV * FSTR + row * FSTR + c * 8) * 2;
            cp_async16(ksa + so,
                       Kh + ((size_t)(b * SEQ) + kv0 + row) * DMODEL + h * 64 + c * 8);
            cp_async16(vsa + so,
                       Vt + ((size_t)((b * 16 + h) * 64) + row) * SEQ + kv0 + c * 8);
        }
        CP_COMMIT();
        if (tid < FBKV)
            Ms[buf][tid] = am[b * SEQ + kv0 + tid] ? 0.0f : -1e30f;
    };

    issue(0, 0);

    for (int kb = 0; kb < nkb; kb++) {
        if (kb + 1 < nkb) { issue((kb + 1) & 1, kb + 1); CP_WAIT1(); }
        else              { CP_WAIT0(); }
        __syncthreads();

        const int buf = kb & 1;
        const int kv0 = kb * FBKV;

        if (kv0 <= qw0 + 31) {                    // warp has unmasked work
            // ---- S = Q K^T ----
            float s[2][8][4];
#pragma unroll
            for (int mt = 0; mt < 2; mt++)
#pragma unroll
                for (int nt = 0; nt < 8; nt++)
#pragma unroll
                    for (int r = 0; r < 4; r++) s[mt][nt][r] = 0.0f;

#pragma unroll
            for (int kt = 0; kt < 4; kt++) {
                uint32_t bf[8][2];
#pragma unroll
                for (int nt = 0; nt < 8; nt++) {
                    const __half* p = &Ks[buf][(nt * 8 + gid) * FSTR + kt * 16 + 2 * tig];
                    bf[nt][0] = *(const uint32_t*)p;
                    bf[nt][1] = *(const uint32_t*)(p + 8);
                }
#pragma unroll
                for (int mt = 0; mt < 2; mt++)
#pragma unroll
                    for (int nt = 0; nt < 8; nt++)
                        mma_f16_16n8k16(s[mt][nt], qf[mt][kt], bf[nt]);
            }

            // ---- mask + online softmax ----
#pragma unroll
            for (int mt = 0; mt < 2; mt++)
#pragma unroll
                for (int r = 0; r < 2; r++) {
                    const int row = qw0 + mt * 16 + gid + r * 8;
                    float mx = -1e30f;
#pragma unroll
                    for (int nt = 0; nt < 8; nt++)
#pragma unroll
                        for (int c = 0; c < 2; c++) {
                            const int jl = nt * 8 + 2 * tig + c;
                            float v = s[mt][nt][r * 2 + c] + Ms[buf][jl];
                            if (kv0 + jl > row) v = -1e30f;
                            s[mt][nt][r * 2 + c] = v;
                            mx = fmaxf(mx, v);
                        }
                    mx = fmaxf(mx, __shfl_xor_sync(0xffffffff, mx, 1));
                    mx = fmaxf(mx, __shfl_xor_sync(0xffffffff, mx, 2));
                    const float mnew = fmaxf(m_run[mt][r], mx);
                    const float corr = __expf(m_run[mt][r] - mnew);
                    m_run[mt][r] = mnew;
                    lp[mt][r] *= corr;
                    float ls = 0.0f;
#pragma unroll
                    for (int nt = 0; nt < 8; nt++) {
                        o[mt][nt][r * 2]     *= corr;
                        o[mt][nt][r * 2 + 1] *= corr;
                        float p0 = __expf(s[mt][nt][r * 2]     - mnew);
                        float p1 = __expf(s[mt][nt][r * 2 + 1] - mnew);
                        s[mt][nt][r * 2]     = p0;
                        s[mt][nt][r * 2 + 1] = p1;
                        ls += p0 + p1;
                    }
                    lp[mt][r] += ls;
                }

            // ---- O += P V  (S-frag -> A-frag reuse) ----
#pragma unroll
            for (int kt = 0; kt < 4; kt++) {
                uint32_t bfv[8][2];
#pragma unroll
                for (int nt = 0; nt < 8; nt++) {
                    const __half* p = &Vs[buf][(nt * 8 + gid) * FSTR + kt * 16 + 2 * tig];
                    bfv[nt][0] = *(const uint32_t*)p;
                    bfv[nt][1] = *(const uint32_t*)(p + 8);
                }
#pragma unroll
                for (int mt = 0; mt < 2; mt++) {
                    uint32_t pa[4];
                    pa[0] = h2u(s[mt][2 * kt][0],     s[mt][2 * kt][1]);
                    pa[1] = h2u(s[mt][2 * kt][2],     s[mt][2 * kt][3]);
                    pa[2] = h2u(s[mt][2 * kt + 1][0], s[mt][2 * kt + 1][1]);
                    pa[3] = h2u(s[mt][2 * kt + 1][2], s[mt][2 * kt + 1][3]);
#pragma unroll
                    for (int nt = 0; nt < 8; nt++)
                        mma_f16_16n8k16(o[mt][nt], pa, bfv[nt]);
                }
            }
        }
        __syncthreads();
    }

    // ---- epilogue ----
#pragma unroll
    for (int mt = 0; mt < 2; mt++)
#pragma unroll
        for (int r = 0; r < 2; r++) {
            float l = lp[mt][r];
            l += __shfl_xor_sync(0xffffffff, l, 1);
            l += __shfl_xor_sync(0xffffffff, l, 2);
            const float inv = 1.0f / l;
            const int row = qw0 + mt * 16 + gid + r * 8;
            __half* orow = O + ((size_t)(b * SEQ) + row) * DMODEL + h * 64;
#pragma unroll
            for (int nt = 0; nt < 8; nt++)
                *(__half2*)&orow[nt * 8 + 2 * tig] =
                    __floats2half2_rn(o[mt][nt][r * 2] * inv,
                                      o[mt][nt][r * 2 + 1] * inv);
        }
}

// ---------------------------------------------------------------------------
extern "C" void kernel_launch(void* const* d_in, const int* in_sizes, int n_in,
                              void* d_out, int out_size) {
    const float* x  = (const float*)d_in[0];
    const int*   am = (const int*)  d_in[1];
    const float* w[4] = { (const float*)d_in[2], (const float*)d_in[3],
                          (const float*)d_in[4], (const float*)d_in[5] };
    float* out = (float*)d_out;

    __half *xh, *qh, *kh, *vh, *vt, *oh, *wh;
    cudaGetSymbolAddress((void**)&xh, g_xh);
    cudaGetSymbolAddress((void**)&qh, g_qh);
    cudaGetSymbolAddress((void**)&kh, g_kh);
    cudaGetSymbolAddress((void**)&vh, g_vh);
    cudaGetSymbolAddress((void**)&vt, g_vt);
    cudaGetSymbolAddress((void**)&oh, g_oh);
    cudaGetSymbolAddress((void**)&wh, g_wh);

    cudaFuncSetAttribute(gemm_h_kernel<__half>,
                         cudaFuncAttributeMaxDynamicSharedMemorySize, SMEM_GEMM);
    cudaFuncSetAttribute(gemm_h_kernel<float>,
                         cudaFuncAttributeMaxDynamicSharedMemorySize, SMEM_GEMM);

    {
        int n4 = MROWS * DMODEL / 4;
        f2h_kernel<<<(n4 + 255) / 256, 256>>>(x, xh, n4);
        int w4 = DMODEL * DMODEL / 4;
        for (int i = 0; i < 4; i++)
            f2h_kernel<<<(w4 + 255) / 256, 256>>>(w[i], wh + (size_t)i * DMODEL * DMODEL, w4);
    }

    dim3 gg(DMODEL / GBN, MROWS / GBM);   // (8, 64)
    gemm_h_kernel<__half><<<gg, 256, SMEM_GEMM>>>(
        xh, wh + 0 * (size_t)DMODEL * DMODEL, qh, 0.125f);
    gemm_h_kernel<__half><<<gg, 256, SMEM_GEMM>>>(
        xh, wh + 1 * (size_t)DMODEL * DMODEL, kh, 1.0f);
    gemm_h_kernel<__half><<<gg, 256, SMEM_GEMM>>>(
        xh, wh + 2 * (size_t)DMODEL * DMODEL, vh, 1.0f);

    dim3 tg(SEQ / 64, NHEADS, BATCH);
    vtrans_kernel<<<tg, 256>>>(vh, vt);

    dim3 fg(SEQ / 128, NHEADS, BATCH);    // (16, 16, 4)
    flash_tc_kernel<<<fg, 128>>>(qh, kh, vt, am, oh);

    gemm_h_kernel<float><<<gg, 256, SMEM_GEMM>>>(
        oh, wh + 3 * (size_t)DMODEL * DMODEL, out, 1.0f);
}

// round 9
// speedup vs baseline: 9.2309x; 1.0940x over previous
#include <cuda_runtime.h>
#include <cuda_fp16.h>
#include <cstdint>
#include <math.h>

#define BATCH  4
#define SEQ    2048
#define DMODEL 1024
#define NHEADS 16
#define HDIM   64
#define MROWS  (BATCH * SEQ)

// Scratch (allocation-free)
__device__ __half g_xh[MROWS * DMODEL];
__device__ __half g_qh[MROWS * DMODEL];
__device__ __half g_kh[MROWS * DMODEL];
__device__ __half g_vh[MROWS * DMODEL];
__device__ __half g_vt[MROWS * DMODEL];       // V^T per (b,h): [(b*16+h)*64+d][s]
__device__ __half g_oh[MROWS * DMODEL];
__device__ __half g_wh[4][DMODEL * DMODEL];   // wq, wk, wv, wo as fp16

// ---------------------------------------------------------------------------
// Helpers
// ---------------------------------------------------------------------------
__device__ __forceinline__ uint32_t smem_u32(const void* p) {
    uint32_t a;
    asm("{ .reg .u64 t; cvta.to.shared.u64 t, %1; cvt.u32.u64 %0, t; }"
        : "=r"(a) : "l"(p));
    return a;
}

__device__ __forceinline__ void cp_async16(uint32_t dst, const void* src) {
    asm volatile("cp.async.cg.shared.global [%0], [%1], 16;"
                 :: "r"(dst), "l"(src));
}
#define CP_COMMIT() asm volatile("cp.async.commit_group;" ::: "memory")
#define CP_WAIT1()  asm volatile("cp.async.wait_group 1;" ::: "memory")
#define CP_WAIT0()  asm volatile("cp.async.wait_group 0;" ::: "memory")

__device__ __forceinline__ void mma_f16_16n8k16(float* c, const uint32_t* a,
                                                const uint32_t* b) {
    asm volatile(
        "mma.sync.aligned.m16n8k16.row.col.f32.f16.f16.f32 "
        "{%0,%1,%2,%3}, {%4,%5,%6,%7}, {%8,%9}, {%0,%1,%2,%3};"
        : "+f"(c[0]), "+f"(c[1]), "+f"(c[2]), "+f"(c[3])
        : "r"(a[0]), "r"(a[1]), "r"(a[2]), "r"(a[3]), "r"(b[0]), "r"(b[1]));
}

__device__ __forceinline__ void ldsm_x4(uint32_t& r0, uint32_t& r1,
                                        uint32_t& r2, uint32_t& r3,
                                        uint32_t addr) {
    asm volatile("ldmatrix.sync.aligned.m8n8.x4.shared.b16 {%0,%1,%2,%3}, [%4];"
                 : "=r"(r0), "=r"(r1), "=r"(r2), "=r"(r3) : "r"(addr));
}

__device__ __forceinline__ uint32_t h2u(float a, float b) {
    __half2 h = __floats2half2_rn(a, b);
    return *(uint32_t*)&h;
}

// ---------------------------------------------------------------------------
// fp32 -> fp16 converters
// ---------------------------------------------------------------------------
__global__ void f2h_kernel(const float* __restrict__ s, __half* __restrict__ d,
                           int n4) {
    int i = blockIdx.x * blockDim.x + threadIdx.x;
    if (i < n4) {
        float4 v = ((const float4*)s)[i];
        ((__half2*)d)[2 * i]     = __floats2half2_rn(v.x, v.y);
        ((__half2*)d)[2 * i + 1] = __floats2half2_rn(v.z, v.w);
    }
}

__global__ void f2h4_kernel(const float* __restrict__ w0,
                            const float* __restrict__ w1,
                            const float* __restrict__ w2,
                            const float* __restrict__ w3,
                            __half* __restrict__ d, int n4) {
    const int j = blockIdx.y;
    const float* s = (j == 0) ? w0 : (j == 1) ? w1 : (j == 2) ? w2 : w3;
    __half* dd = d + (size_t)j * DMODEL * DMODEL;
    int i = blockIdx.x * blockDim.x + threadIdx.x;
    if (i < n4) {
        float4 v = ((const float4*)s)[i];
        ((__half2*)dd)[2 * i]     = __floats2half2_rn(v.x, v.y);
        ((__half2*)dd)[2 * i + 1] = __floats2half2_rn(v.z, v.w);
    }
}

// ---------------------------------------------------------------------------
// V transpose: v[b*SEQ+s][h*64+d] -> vt[(b*16+h)*64+d][s]
// ---------------------------------------------------------------------------
__global__ __launch_bounds__(256)
void vtrans_kernel(const __half* __restrict__ v, __half* __restrict__ vt) {
    __shared__ __half t[64][72];
    const int tid = threadIdx.x;
    const int s0 = blockIdx.x * 64;
    const int h  = blockIdx.y;
    const int b  = blockIdx.z;
#pragma unroll
    for (int i = 0; i < 2; i++) {
        int idx = tid + i * 256, row = idx >> 3, c = idx & 7;
        *(int4*)&t[row][c * 8] =
            *(const int4*)&v[((size_t)(b * SEQ) + s0 + row) * DMODEL + h * 64 + c * 8];
    }
    __syncthreads();
#pragma unroll
    for (int i = 0; i < 2; i++) {
        int idx = tid + i * 256, d = idx >> 3, c = idx & 7;
        __half tmp[8];
#pragma unroll
        for (int k = 0; k < 8; k++) tmp[k] = t[c * 8 + k][d];
        *(int4*)&vt[((size_t)((b * 16 + h) * 64) + d) * SEQ + s0 + c * 8] =
            *(int4*)tmp;
    }
}

// ===========================================================================
// fp16 tensor-core GEMM:  C[M,1024] = scale * (A(f16) @ B(f16)^T)
// CTA 128x128, BK=64, 8 warps, warp 64x32, 3-stage cp.async, ldmatrix loads.
// ===========================================================================
#define GBM 128
#define GBN 128
#define BKH 64
#define SSTRH 72
#define STAGE_BYTES (2 * 128 * SSTRH * 2)        // 36864
#define SMEM_GEMM   (3 * STAGE_BYTES)            // 110592

template <typename OutT>
__device__ __forceinline__ void gemm_body(const __half* __restrict__ A,
                                          const __half* __restrict__ Bw,
                                          OutT* __restrict__ C, float scale,
                                          char* smemc) {
    const uint32_t sb = smem_u32(smemc);
    const int K = DMODEL, N = DMODEL;
    const int tid = threadIdx.x;
    const int wid = tid >> 5;
    const int lid = tid & 31;
    const int gid = lid >> 2;
    const int tig = lid & 3;
    const int wm  = wid >> 2;
    const int wn  = wid & 3;
    const int m0  = blockIdx.y * GBM;
    const int n0  = blockIdx.x * GBN;

    float acc[4][4][4];
#pragma unroll
    for (int i = 0; i < 4; i++)
#pragma unroll
        for (int j = 0; j < 4; j++)
#pragma unroll
            for (int r = 0; r < 4; r++) acc[i][j][r] = 0.0f;

    auto issue = [&](int stage, int ck) {
        const __half* Ag = A  + (size_t)m0 * K + ck * BKH;
        const __half* Bg = Bw + (size_t)n0 * K + ck * BKH;
        const uint32_t da = sb + stage * STAGE_BYTES;
        const uint32_t db = da + 128 * SSTRH * 2;
#pragma unroll
        for (int i = 0; i < 4; i++) {
            int idx = tid + i * 256;
            int row = idx >> 3;
            int c   = idx & 7;
            uint32_t so = (uint32_t)(row * SSTRH + c * 8) * 2;
            cp_async16(da + so, Ag + (size_t)row * K + c * 8);
            cp_async16(db + so, Bg + (size_t)row * K + c * 8);
        }
        CP_COMMIT();
    };

    const int NCH = K / BKH;                     // 16
    issue(0, 0);
    issue(1, 1);

    // ldmatrix lane-address components
    const int a_row = lid & 15;                  // row within m16
    const int a_col = (lid >> 4) * 8;            // 0 or 8 (k)
    const int b_row = (lid & 7) + ((lid >> 4) & 1) * 8;  // row within n16
    const int b_col = ((lid >> 3) & 1) * 8;      // 0 or 8 (k)

    for (int ck = 0; ck < NCH; ck++) {
        if (ck + 1 < NCH) { CP_WAIT1(); } else { CP_WAIT0(); }
        __syncthreads();
        if (ck + 2 < NCH) issue((ck + 2) % 3, ck + 2);

        const uint32_t bufA = sb + (ck % 3) * STAGE_BYTES;
        const uint32_t bufB = bufA + 128 * SSTRH * 2;

#pragma unroll
        for (int kk = 0; kk < 4; kk++) {
            const int koff = kk * 16;
            uint32_t af[4][4], bf[4][2];
#pragma unroll
            for (int mt = 0; mt < 4; mt++) {
                uint32_t ad = bufA + 2 * (uint32_t)((wm * 64 + mt * 16 + a_row) * SSTRH
                                                    + koff + a_col);
                ldsm_x4(af[mt][0], af[mt][1], af[mt][2], af[mt][3], ad);
            }
#pragma unroll
            for (int p = 0; p < 2; p++) {
                uint32_t bd = bufB + 2 * (uint32_t)((wn * 32 + p * 16 + b_row) * SSTRH
                                                    + koff + b_col);
                ldsm_x4(bf[2 * p][0], bf[2 * p][1], bf[2 * p + 1][0],
                        bf[2 * p + 1][1], bd);
            }
#pragma unroll
            for (int mt = 0; mt < 4; mt++)
#pragma unroll
                for (int nt = 0; nt < 4; nt++)
                    mma_f16_16n8k16(acc[mt][nt], af[mt], bf[nt]);
        }
    }

#pragma unroll
    for (int mt = 0; mt < 4; mt++) {
#pragma unroll
        for (int nt = 0; nt < 4; nt++) {
            int row = m0 + wm * 64 + mt * 16 + gid;
            int col = n0 + wn * 32 + nt * 8 + 2 * tig;
            if (sizeof(OutT) == 4) {
                float* Cf = (float*)C;
                *(float2*)&Cf[(size_t)row * N + col] =
                    make_float2(acc[mt][nt][0] * scale, acc[mt][nt][1] * scale);
                *(float2*)&Cf[(size_t)(row + 8) * N + col] =
                    make_float2(acc[mt][nt][2] * scale, acc[mt][nt][3] * scale);
            } else {
                __half* Ch = (__half*)C;
                *(__half2*)&Ch[(size_t)row * N + col] =
                    __floats2half2_rn(acc[mt][nt][0] * scale, acc[mt][nt][1] * scale);
                *(__half2*)&Ch[(size_t)(row + 8) * N + col] =
                    __floats2half2_rn(acc[mt][nt][2] * scale, acc[mt][nt][3] * scale);
            }
        }
    }
}

// Fused QKV: grid (8, 64, 3)
__global__ __launch_bounds__(256)
void gemm_qkv_kernel(const __half* __restrict__ xh,
                     const __half* __restrict__ whBase,
                     __half* __restrict__ qh, __half* __restrict__ kh,
                     __half* __restrict__ vh) {
    extern __shared__ char smemc[];
    const int slot = blockIdx.z;
    const __half* Bw = whBase + (size_t)slot * DMODEL * DMODEL;
    __half* C = (slot == 0) ? qh : (slot == 1) ? kh : vh;
    const float scale = (slot == 0) ? 0.125f : 1.0f;
    gemm_body<__half>(xh, Bw, C, scale, smemc);
}

__global__ __launch_bounds__(256)
void gemm_out_kernel(const __half* __restrict__ A,
                     const __half* __restrict__ Bw,
                     float* __restrict__ C) {
    extern __shared__ char smemc[];
    gemm_body<float>(A, Bw, C, 1.0f, smemc);
}

// ===========================================================================
// Tensor-core flash attention (FA2 fragment reuse), ldmatrix K/V loads.
// grid (SEQ/128, NHEADS, BATCH), 128 threads = 4 warps; warp: 32 q-rows.
// Pipeline ordering: issue(next) BEFORE wait (2 groups in flight -> WAIT1
// retires the tile we consume); trailing sync separates read from overwrite.
// ===========================================================================
#define FBKV 64
#define FSTR 72

__global__ __launch_bounds__(128)
void flash_tc_kernel(const __half* __restrict__ Qh,
                     const __half* __restrict__ Kh,
                     const __half* __restrict__ Vt,
                     const int*   __restrict__ am,
                     __half* __restrict__ O) {
    __shared__ __half Ks[2][FBKV * FSTR];
    __shared__ __half Vs[2][FBKV * FSTR];
    __shared__ float  Ms[2][FBKV];

    const int tid = threadIdx.x;
    const int wid = tid >> 5;
    const int lid = tid & 31;
    const int gid = lid >> 2;
    const int tig = lid & 3;
    const int q0  = blockIdx.x * 128;
    const int h   = blockIdx.y;
    const int b   = blockIdx.z;
    const int qw0 = q0 + wid * 32;

    const uint32_t ksa = smem_u32(Ks);
    const uint32_t vsa = smem_u32(Vs);
    const int b_row = (lid & 7) + ((lid >> 4) & 1) * 8;
    const int b_col = ((lid >> 3) & 1) * 8;

    // Q fragments: 2 m-tiles x 4 k-tiles.
    uint32_t qf[2][4][4];
#pragma unroll
    for (int mt = 0; mt < 2; mt++)
#pragma unroll
        for (int kt = 0; kt < 4; kt++) {
            const __half* base = Qh + ((size_t)(b * SEQ) + qw0 + mt * 16 + gid) * DMODEL
                                    + h * 64 + kt * 16 + 2 * tig;
            qf[mt][kt][0] = *(const uint32_t*)base;
            qf[mt][kt][1] = *(const uint32_t*)(base + 8 * DMODEL);
            qf[mt][kt][2] = *(const uint32_t*)(base + 8);
            qf[mt][kt][3] = *(const uint32_t*)(base + 8 * DMODEL + 8);
        }

    float o[2][8][4];
#pragma unroll
    for (int mt = 0; mt < 2; mt++)
#pragma unroll
        for (int nt = 0; nt < 8; nt++)
#pragma unroll
            for (int r = 0; r < 4; r++) o[mt][nt][r] = 0.0f;
    float m_run[2][2] = { { -1e30f, -1e30f }, { -1e30f, -1e30f } };
    float lp[2][2]    = { { 0.0f, 0.0f }, { 0.0f, 0.0f } };

    const int nkb = (q0 + 128) / FBKV;

    auto issue = [&](int buf, int kb) {
        const int kv0 = kb * FBKV;
#pragma unroll
        for (int i = 0; i < 4; i++) {
            int idx = tid + i * 128;
            int row = idx >> 3;
            int c   = idx & 7;
            uint32_t so = (uint32_t)(buf * FBKV * FSTR + row * FSTR + c * 8) * 2;
            cp_async16(ksa + so,
                       Kh + ((size_t)(b * SEQ) + kv0 + row) * DMODEL + h * 64 + c * 8);
            cp_async16(vsa + so,
                       Vt + ((size_t)((b * 16 + h) * 64) + row) * SEQ + kv0 + c * 8);
        }
        CP_COMMIT();
        if (tid < FBKV)
            Ms[buf][tid] = am[b * SEQ + kv0 + tid] ? 0.0f : -1e30f;
    };

    issue(0, 0);

    for (int kb = 0; kb < nkb; kb++) {
        if (kb + 1 < nkb) { issue((kb + 1) & 1, kb + 1); CP_WAIT1(); }
        else              { CP_WAIT0(); }
        __syncthreads();

        const int buf = kb & 1;
        const int kv0 = kb * FBKV;
        const uint32_t kbase = ksa + (uint32_t)(buf * FBKV * FSTR) * 2;
        const uint32_t vbase = vsa + (uint32_t)(buf * FBKV * FSTR) * 2;

        if (kv0 <= qw0 + 31) {                    // warp has unmasked work
            // ---- S = Q K^T ----
            float s[2][8][4];
#pragma unroll
            for (int mt = 0; mt < 2; mt++)
#pragma unroll
                for (int nt = 0; nt < 8; nt++)
#pragma unroll
                    for (int r = 0; r < 4; r++) s[mt][nt][r] = 0.0f;

#pragma unroll
            for (int kt = 0; kt < 4; kt++) {
                uint32_t bf[8][2];
#pragma unroll
                for (int p = 0; p < 4; p++) {
                    uint32_t ad = kbase + 2 * (uint32_t)((p * 16 + b_row) * FSTR
                                                         + kt * 16 + b_col);
                    ldsm_x4(bf[2 * p][0], bf[2 * p][1], bf[2 * p + 1][0],
                            bf[2 * p + 1][1], ad);
                }
#pragma unroll
                for (int mt = 0; mt < 2; mt++)
#pragma unroll
                    for (int nt = 0; nt < 8; nt++)
                        mma_f16_16n8k16(s[mt][nt], qf[mt][kt], bf[nt]);
            }

            // ---- mask + online softmax ----
#pragma unroll
            for (int mt = 0; mt < 2; mt++)
#pragma unroll
                for (int r = 0; r < 2; r++) {
                    const int row = qw0 + mt * 16 + gid + r * 8;
                    float mx = -1e30f;
#pragma unroll
                    for (int nt = 0; nt < 8; nt++)
#pragma unroll
                        for (int c = 0; c < 2; c++) {
                            const int jl = nt * 8 + 2 * tig + c;
                            float v = s[mt][nt][r * 2 + c] + Ms[buf][jl];
                            if (kv0 + jl > row) v = -1e30f;
                            s[mt][nt][r * 2 + c] = v;
                            mx = fmaxf(mx, v);
                        }
                    mx = fmaxf(mx, __shfl_xor_sync(0xffffffff, mx, 1));
                    mx = fmaxf(mx, __shfl_xor_sync(0xffffffff, mx, 2));
                    const float mnew = fmaxf(m_run[mt][r], mx);
                    const float corr = __expf(m_run[mt][r] - mnew);
                    m_run[mt][r] = mnew;
                    lp[mt][r] *= corr;
                    float ls = 0.0f;
#pragma unroll
                    for (int nt = 0; nt < 8; nt++) {
                        o[mt][nt][r * 2]     *= corr;
                        o[mt][nt][r * 2 + 1] *= corr;
                        float p0 = __expf(s[mt][nt][r * 2]     - mnew);
                        float p1 = __expf(s[mt][nt][r * 2 + 1] - mnew);
                        s[mt][nt][r * 2]     = p0;
                        s[mt][nt][r * 2 + 1] = p1;
                        ls += p0 + p1;
                    }
                    lp[mt][r] += ls;
                }

            // ---- O += P V ----
#pragma unroll
            for (int kt = 0; kt < 4; kt++) {
                uint32_t bfv[8][2];
#pragma unroll
                for (int p = 0; p < 4; p++) {
                    uint32_t ad = vbase + 2 * (uint32_t)((p * 16 + b_row) * FSTR
                                                         + kt * 16 + b_col);
                    ldsm_x4(bfv[2 * p][0], bfv[2 * p][1], bfv[2 * p + 1][0],
                            bfv[2 * p + 1][1], ad);
                }
#pragma unroll
                for (int mt = 0; mt < 2; mt++) {
                    uint32_t pa[4];
                    pa[0] = h2u(s[mt][2 * kt][0],     s[mt][2 * kt][1]);
                    pa[1] = h2u(s[mt][2 * kt][2],     s[mt][2 * kt][3]);
                    pa[2] = h2u(s[mt][2 * kt + 1][0], s[mt][2 * kt + 1][1]);
                    pa[3] = h2u(s[mt][2 * kt + 1][2], s[mt][2 * kt + 1][3]);
#pragma unroll
                    for (int nt = 0; nt < 8; nt++)
                        mma_f16_16n8k16(o[mt][nt], pa, bfv[nt]);
                }
            }
        }
        __syncthreads();   // all warps done with buf before next issue overwrites it
    }

    // ---- epilogue ----
#pragma unroll
    for (int mt = 0; mt < 2; mt++)
#pragma unroll
        for (int r = 0; r < 2; r++) {
            float l = lp[mt][r];
            l += __shfl_xor_sync(0xffffffff, l, 1);
            l += __shfl_xor_sync(0xffffffff, l, 2);
            const float inv = 1.0f / l;
            const int row = qw0 + mt * 16 + gid + r * 8;
            __half* orow = O + ((size_t)(b * SEQ) + row) * DMODEL + h * 64;
#pragma unroll
            for (int nt = 0; nt < 8; nt++)
                *(__half2*)&orow[nt * 8 + 2 * tig] =
                    __floats2half2_rn(o[mt][nt][r * 2] * inv,
                                      o[mt][nt][r * 2 + 1] * inv);
        }
}

// ---------------------------------------------------------------------------
extern "C" void kernel_launch(void* const* d_in, const int* in_sizes, int n_in,
                              void* d_out, int out_size) {
    const float* x  = (const float*)d_in[0];
    const int*   am = (const int*)  d_in[1];
    float* out = (float*)d_out;

    __half *xh, *qh, *kh, *vh, *vt, *oh, *wh;
    cudaGetSymbolAddress((void**)&xh, g_xh);
    cudaGetSymbolAddress((void**)&qh, g_qh);
    cudaGetSymbolAddress((void**)&kh, g_kh);
    cudaGetSymbolAddress((void**)&vh, g_vh);
    cudaGetSymbolAddress((void**)&vt, g_vt);
    cudaGetSymbolAddress((void**)&oh, g_oh);
    cudaGetSymbolAddress((void**)&wh, g_wh);

    cudaFuncSetAttribute(gemm_qkv_kernel,
                         cudaFuncAttributeMaxDynamicSharedMemorySize, SMEM_GEMM);
    cudaFuncSetAttribute(gemm_out_kernel,
                         cudaFuncAttributeMaxDynamicSharedMemorySize, SMEM_GEMM);

    {
        int n4 = MROWS * DMODEL / 4;
        f2h_kernel<<<(n4 + 255) / 256, 256>>>(x, xh, n4);
        int w4 = DMODEL * DMODEL / 4;
        dim3 wg((w4 + 255) / 256, 4);
        f2h4_kernel<<<wg, 256>>>((const float*)d_in[2], (const float*)d_in[3],
                                 (const float*)d_in[4], (const float*)d_in[5],
                                 wh, w4);
    }

    dim3 gq(DMODEL / GBN, MROWS / GBM, 3);    // (8, 64, 3)
    gemm_qkv_kernel<<<gq, 256, SMEM_GEMM>>>(xh, wh, qh, kh, vh);

    dim3 tg(SEQ / 64, NHEADS, BATCH);
    vtrans_kernel<<<tg, 256>>>(vh, vt);

    dim3 fg(SEQ / 128, NHEADS, BATCH);        // (16, 16, 4)
    flash_tc_kernel<<<fg, 128>>>(qh, kh, vt, am, oh);

    dim3 gg(DMODEL / GBN, MROWS / GBM);       // (8, 64)
    gemm_out_kernel<<<gg, 256, SMEM_GEMM>>>(
        oh, wh + 3 * (size_t)DMODEL * DMODEL, out);
}